// round 14
// baseline (speedup 1.0000x reference)
#include <cuda_runtime.h>
#include <cuda_bf16.h>
#include <stdint.h>
#include <math.h>

#define NN   50000
#define EE   800000
#define ETOT (EE + NN)
#define HIDD 128
#define NHH  8
#define NLL  3
#define NGG  64
#define NCC  3

// ---------------- scratch (static device globals) ----------------
__device__ float g_h [(size_t)NN*HIDD];
__device__ float g_z [(size_t)NN*NHH*HIDD];
__device__ float g_as[(size_t)NN*NHH];
__device__ float g_ad[(size_t)NN*NHH];
__device__ float g_q [16*HIDD];
__device__ float g_gi[(size_t)NN*3*HIDD];
__device__ float g_gh[(size_t)NN*3*HIDD];
__device__ float g_pool[NGG*HIDD];
__device__ float g_cnt [NGG];
__device__ int   g_deg [NN];
__device__ int   g_off [NN+1];
__device__ int   g_cur [NN];
__device__ int   g_esrc[ETOT];
__device__ __nv_bfloat16 g_bhi[128*1024];
__device__ __nv_bfloat16 g_blo[128*1024];

// ---------------- mma/ldmatrix helpers (baseline PTX, sm_80+) ----------
__device__ __forceinline__ uint32_t smem_u32(const void* p) {
    uint32_t a;
    asm("{ .reg .u64 t; cvta.to.shared.u64 t, %1; cvt.u32.u64 %0, t; }" : "=r"(a) : "l"(p));
    return a;
}
__device__ __forceinline__ void ldm4(uint32_t* r, uint32_t addr) {
    asm volatile("ldmatrix.sync.aligned.m8n8.x4.shared.b16 {%0,%1,%2,%3}, [%4];"
        : "=r"(r[0]), "=r"(r[1]), "=r"(r[2]), "=r"(r[3]) : "r"(addr));
}
__device__ __forceinline__ void mma16816(float* c, const uint32_t* a, const uint32_t* b) {
    asm volatile("mma.sync.aligned.m16n8k16.row.col.f32.bf16.bf16.f32 "
        "{%0,%1,%2,%3}, {%4,%5,%6,%7}, {%8,%9}, {%0,%1,%2,%3};"
        : "+f"(c[0]), "+f"(c[1]), "+f"(c[2]), "+f"(c[3])
        : "r"(a[0]), "r"(a[1]), "r"(a[2]), "r"(a[3]), "r"(b[0]), "r"(b[1]));
}
__device__ __forceinline__ unsigned pk(__nv_bfloat16 a, __nv_bfloat16 b) {
    unsigned short ua = *(unsigned short*)&a, ub = *(unsigned short*)&b;
    return (unsigned)ua | ((unsigned)ub << 16);
}

// ---------------- tensor-core GEMM via mma.sync -------------------------
// C[M,Nout] = relu?( scale * (A[M,K] @ B^T) + bias ), B[Nout,K] pre-split bf16.
// fp32 emulation: virtual K' = 3K with A' = [Ahi|Ahi|Alo], B' = [Bhi|Blo|Bhi].
// Block 128x128, BK=32, 256 threads (8 warps: 4M x 2N), warp tile 32x64.
#define SMS 40   // smem row stride (bf16 elems): 80B, conflict-free ldmatrix
__global__ __launch_bounds__(256) void gemm_mma(
    const float* __restrict__ A,
    const __nv_bfloat16* __restrict__ Bhi, const __nv_bfloat16* __restrict__ Blo,
    const float* __restrict__ bias, float* __restrict__ C,
    int M, int K, int Nout, float scale, int relu)
{
    __shared__ __align__(16) __nv_bfloat16 As[128 * SMS];
    __shared__ __align__(16) __nv_bfloat16 Bs[128 * SMS];
    const int tid = threadIdx.x;
    const int wid = tid >> 5, lane = tid & 31;
    const int m0 = blockIdx.y * 128;
    const int n0 = blockIdx.x * 128;
    const int Mbase = (wid >> 1) * 32;
    const int Nbase = (wid & 1) * 64;
    const uint32_t smA = smem_u32(As), smB = smem_u32(Bs);

    float acc[2][8][4];
    #pragma unroll
    for (int i = 0; i < 2; i++)
        #pragma unroll
        for (int j = 0; j < 8; j++)
            #pragma unroll
            for (int k = 0; k < 4; k++) acc[i][j][k] = 0.f;

    const int lrow = tid >> 1;              // loader row 0..127
    const int lcol = (tid & 1) * 16;        // col half
    const bool avalid = (m0 + lrow) < M;
    const int nckpt = K >> 5;

    for (int term = 0; term < 3; term++) {
        const bool alo = (term == 2);
        const __nv_bfloat16* Bsrc = (term == 1) ? Blo : Bhi;
        for (int c = 0; c < nckpt; c++) {
            const int kc = c << 5;
            // stage A: 128x32 f32 -> bf16 (hi or lo part)
            {
                const float4* ap = (const float4*)(A + (size_t)(m0 + lrow) * K + kc + lcol);
                #pragma unroll
                for (int j = 0; j < 4; j++) {
                    float4 v = avalid ? ap[j] : make_float4(0.f, 0.f, 0.f, 0.f);
                    __nv_bfloat16 hx = __float2bfloat16(v.x), hy = __float2bfloat16(v.y);
                    __nv_bfloat16 hz = __float2bfloat16(v.z), hw = __float2bfloat16(v.w);
                    unsigned u0, u1;
                    if (!alo) { u0 = pk(hx, hy); u1 = pk(hz, hw); }
                    else {
                        u0 = pk(__float2bfloat16(v.x - __bfloat162float(hx)),
                                __float2bfloat16(v.y - __bfloat162float(hy)));
                        u1 = pk(__float2bfloat16(v.z - __bfloat162float(hz)),
                                __float2bfloat16(v.w - __bfloat162float(hw)));
                    }
                    uint2 st; st.x = u0; st.y = u1;
                    *(uint2*)&As[lrow * SMS + lcol + j * 4] = st;
                }
            }
            // stage B: 128x32 bf16
            {
                const uint4* bp = (const uint4*)(Bsrc + (size_t)(n0 + lrow) * K + kc + lcol);
                #pragma unroll
                for (int j = 0; j < 2; j++)
                    *(uint4*)&Bs[lrow * SMS + lcol + j * 8] = bp[j];
            }
            __syncthreads();

            #pragma unroll
            for (int k16o = 0; k16o < 32; k16o += 16) {
                uint32_t afr[2][4], bfr[8][2];
                #pragma unroll
                for (int mi = 0; mi < 2; mi++) {
                    int row = Mbase + mi * 16 + (lane & 15);
                    int col = k16o + ((lane >> 4) << 3);
                    ldm4(afr[mi], smA + (uint32_t)(row * SMS + col) * 2);
                }
                #pragma unroll
                for (int p = 0; p < 4; p++) {
                    int grp = lane >> 3;
                    int n = Nbase + p * 16 + ((grp >> 1) << 3) + (lane & 7);
                    int k = k16o + ((grp & 1) << 3);
                    uint32_t r[4];
                    ldm4(r, smB + (uint32_t)(n * SMS + k) * 2);
                    bfr[2 * p][0] = r[0]; bfr[2 * p][1] = r[1];
                    bfr[2 * p + 1][0] = r[2]; bfr[2 * p + 1][1] = r[3];
                }
                #pragma unroll
                for (int mi = 0; mi < 2; mi++)
                    #pragma unroll
                    for (int ni = 0; ni < 8; ni++)
                        mma16816(acc[mi][ni], afr[mi], bfr[ni]);
            }
            __syncthreads();
        }
    }

    // epilogue: c0,c1 -> (row, col..col+1); c2,c3 -> (row+8, ...)
    #pragma unroll
    for (int mi = 0; mi < 2; mi++) {
        int r0 = m0 + Mbase + mi * 16 + (lane >> 2);
        #pragma unroll
        for (int rr = 0; rr < 2; rr++) {
            int row = r0 + rr * 8;
            if (row >= M) continue;
            #pragma unroll
            for (int ni = 0; ni < 8; ni++) {
                int col = n0 + Nbase + ni * 8 + (lane & 3) * 2;
                float v0 = acc[mi][ni][rr * 2 + 0] * scale + (bias ? bias[col]     : 0.f);
                float v1 = acc[mi][ni][rr * 2 + 1] * scale + (bias ? bias[col + 1] : 0.f);
                if (relu) { v0 = fmaxf(v0, 0.f); v1 = fmaxf(v1, 0.f); }
                float2 o; o.x = v0; o.y = v1;
                *(float2*)(C + (size_t)row * Nout + col) = o;
            }
        }
    }
}

// ---------------- weight pre-split kernels ------------------------------
__global__ void conv_trans128(const float* __restrict__ src,
                              __nv_bfloat16* __restrict__ hi, __nv_bfloat16* __restrict__ lo)
{
    int i = blockIdx.x * blockDim.x + threadIdx.x;
    if (i >= 128 * 128) return;
    float v = src[(i & 127) * 128 + (i >> 7)];
    __nv_bfloat16 h = __float2bfloat16(v);
    hi[i] = h; lo[i] = __float2bfloat16(v - __bfloat162float(h));
}
// B[cout][h*128+k] = W[k][h*128+cout]
__global__ void conv_wl(const float* __restrict__ W,
                        __nv_bfloat16* __restrict__ hi, __nv_bfloat16* __restrict__ lo)
{
    int i = blockIdx.x * blockDim.x + threadIdx.x;
    if (i >= 128 * 1024) return;
    float v = W[(size_t)(i & 127) * 1024 + (((i >> 7) & 7) * 128) + (i >> 10)];
    __nv_bfloat16 h = __float2bfloat16(v);
    hi[i] = h; lo[i] = __float2bfloat16(v - __bfloat162float(h));
}
__global__ void conv_pass(const float* __restrict__ src,
                          __nv_bfloat16* __restrict__ hi, __nv_bfloat16* __restrict__ lo, int n)
{
    int i = blockIdx.x * blockDim.x + threadIdx.x;
    if (i >= n) return;
    float v = src[i];
    __nv_bfloat16 h = __float2bfloat16(v);
    hi[i] = h; lo[i] = __float2bfloat16(v - __bfloat162float(h));
}

// ---------------- CSR build ----------------
__global__ void csr_count(const int* __restrict__ ei, int* __restrict__ deg)
{
    int e = blockIdx.x * blockDim.x + threadIdx.x;
    if (e >= ETOT) return;
    int d = (e < EE) ? ei[EE + e] : (e - EE);
    atomicAdd(&deg[d], 1);
}
__global__ __launch_bounds__(1024) void csr_scan(const int* __restrict__ deg,
                                                 int* __restrict__ off)
{
    const int CHK = (NN + 1023) / 1024;
    int t = threadIdx.x;
    int lo = t * CHK, hi = min(lo + CHK, NN);
    int s = 0;
    for (int i = lo; i < hi; i++) s += deg[i];
    __shared__ int ps[1024];
    ps[t] = s; __syncthreads();
    for (int o = 1; o < 1024; o <<= 1) {
        int v = (t >= o) ? ps[t - o] : 0;
        __syncthreads();
        ps[t] += v;
        __syncthreads();
    }
    int run = (t > 0) ? ps[t - 1] : 0;
    for (int i = lo; i < hi; i++) { off[i] = run; run += deg[i]; }
    if (t == 1023) off[NN] = run;
}
__global__ void csr_scatter(const int* __restrict__ ei, const int* __restrict__ off,
                            int* __restrict__ cur, int* __restrict__ esrc)
{
    int e = blockIdx.x * blockDim.x + threadIdx.x;
    if (e >= ETOT) return;
    int s, d;
    if (e < EE) { s = ei[e]; d = ei[EE + e]; }
    else        { s = e - EE; d = s; }
    int p = atomicAdd(&cur[d], 1);
    esrc[off[d] + p] = s;
}

// ---------------- attention projections ----------------
__global__ void build_q(const float* __restrict__ W, const float* __restrict__ asrc,
                        const float* __restrict__ adst, float* __restrict__ qT)
{
    int w = (blockIdx.x * blockDim.x + threadIdx.x) >> 5;
    int lane = threadIdx.x & 31;
    if (w >= 2048) return;
    int j = w >> 7, k = w & 127;
    int h = j & 7;
    const float* att = ((j < 8) ? asrc : adst) + h * HIDD;
    const float* wr = W + (size_t)k * (NHH * HIDD) + h * HIDD;
    float4 a = *(const float4*)(wr + lane * 4);
    float4 b = *(const float4*)(att + lane * 4);
    float s = a.x*b.x + a.y*b.y + a.z*b.z + a.w*b.w;
    #pragma unroll
    for (int o = 16; o; o >>= 1) s += __shfl_xor_sync(0xffffffffu, s, o);
    if (lane == 0) qT[j * HIDD + k] = s;
}

__global__ __launch_bounds__(256) void alpha2(const float* __restrict__ hf,
                                              const float* __restrict__ qT,
                                              float* __restrict__ as_, float* __restrict__ ad_)
{
    __shared__ float qs[16][HIDD];
    int t = threadIdx.x;
    for (int i = t; i < 16 * HIDD; i += 256) qs[i >> 7][i & 127] = qT[i];
    __syncthreads();
    int n = (blockIdx.x * 256 + t) >> 5;
    int lane = t & 31;
    if (n >= NN) return;
    float4 hv = *(const float4*)(hf + (size_t)n * HIDD + lane * 4);
    #pragma unroll
    for (int j = 0; j < 16; j++) {
        float4 qv = *(const float4*)&qs[j][lane * 4];
        float s = hv.x*qv.x + hv.y*qv.y + hv.z*qv.z + hv.w*qv.w;
        #pragma unroll
        for (int o = 16; o; o >>= 1) s += __shfl_xor_sync(0xffffffffu, s, o);
        if (lane == 0) {
            if (j < 8) as_[(size_t)n * 8 + j] = s;
            else       ad_[(size_t)n * 8 + (j - 8)] = s;
        }
    }
}

// ---------------- CSR edge aggregation ----------------
__global__ __launch_bounds__(128) void edge_agg(
    const int* __restrict__ off, const int* __restrict__ esrc,
    const float* __restrict__ as_, const float* __restrict__ ad_,
    const float* __restrict__ hf, float* __restrict__ zb)
{
    int n = blockIdx.x, t = threadIdx.x, h = t & 7;
    int e0 = off[n], e1 = off[n + 1];
    __shared__ float adn[8];
    __shared__ float den[8];
    __shared__ float red[16][8];
    __shared__ float ws[32][8];
    __shared__ int   ssm[32];
    if (t < 8) adn[t] = ad_[(size_t)n * 8 + t];
    __syncthreads();

    float part = 0.f;
    for (int i = e0 + (t >> 3); i < e1; i += 16) {
        int s = esrc[i];
        float v = as_[(size_t)s * 8 + h] + adn[h];
        v = v > 0.f ? v : 0.2f * v;
        part += __expf(v);
    }
    red[t >> 3][h] = part;
    __syncthreads();
    if (t < 8) {
        float x = 0.f;
        #pragma unroll
        for (int i = 0; i < 16; i++) x += red[i][t];
        den[t] = x;
    }
    __syncthreads();

    float z[8];
    #pragma unroll
    for (int i = 0; i < 8; i++) z[i] = 0.f;

    for (int c0 = e0; c0 < e1; c0 += 32) {
        int m = min(32, e1 - c0);
        for (int i = t >> 3; i < m; i += 16) {
            int s = esrc[c0 + i];
            if (h == 0) ssm[i] = s;
            float v = as_[(size_t)s * 8 + h] + adn[h];
            v = v > 0.f ? v : 0.2f * v;
            ws[i][h] = __expf(v) / (den[h] + 1e-16f);
        }
        __syncthreads();
        for (int i = 0; i < m; i++) {
            float val = hf[(size_t)ssm[i] * HIDD + t];
            #pragma unroll
            for (int hh = 0; hh < 8; hh++) z[hh] += ws[i][hh] * val;
        }
        __syncthreads();
    }
    float* zr = zb + (size_t)n * (NHH * HIDD) + t;
    #pragma unroll
    for (int hh = 0; hh < 8; hh++) zr[hh * HIDD] = z[hh];
}

// ---------------- GRU / pool / classifier ----------------
__global__ void gru_kernel(const float* __restrict__ gi, const float* __restrict__ gh,
                           const float* __restrict__ mem, float* __restrict__ hout)
{
    size_t i = (size_t)blockIdx.x * blockDim.x + threadIdx.x;
    if (i >= (size_t)NN * HIDD) return;
    size_t n = i >> 7; int c = (int)(i & 127);
    const float* a = gi + n * 384;
    const float* b = gh + n * 384;
    float r  = 1.f / (1.f + __expf(-(a[c]       + b[c])));
    float z  = 1.f / (1.f + __expf(-(a[128 + c] + b[128 + c])));
    float nc = tanhf(a[256 + c] + r * b[256 + c]);
    hout[i] = (1.f - z) * nc + z * mem[i];
}

__global__ void pool_kernel(const float* __restrict__ h, const int* __restrict__ batch,
                            float* __restrict__ sums, float* __restrict__ cnt)
{
    const int CHUNK = 500;
    int start = blockIdx.x * CHUNK;
    if (start >= NN) return;
    int end = min(start + CHUNK, NN);
    int c = threadIdx.x;
    int g = batch[start];
    float acc = 0.f, count = 0.f;
    for (int n = start; n < end; n++) {
        int bg = batch[n];
        if (bg != g) {
            atomicAdd(&sums[g * HIDD + c], acc);
            if (c == 0) atomicAdd(&cnt[g], count);
            acc = 0.f; count = 0.f; g = bg;
        }
        acc += h[(size_t)n * HIDD + c];
        count += 1.f;
    }
    atomicAdd(&sums[g * HIDD + c], acc);
    if (c == 0) atomicAdd(&cnt[g], count);
}

__global__ void classifier_kernel(const float* __restrict__ sums, const float* __restrict__ cnt,
                                  const float* __restrict__ c1W, const float* __restrict__ c1b,
                                  const float* __restrict__ c2W, const float* __restrict__ c2b,
                                  float* __restrict__ out)
{
    __shared__ float p[HIDD];
    __shared__ float hid[64];
    __shared__ float lg[3];
    int g = blockIdx.x, t = threadIdx.x;
    float c = fmaxf(cnt[g], 1.f);
    float pv = sums[g * HIDD + t] / c;
    p[t] = pv;
    out[NGG * NCC + g * HIDD + t] = pv;
    __syncthreads();
    if (t < 64) {
        float s = c1b[t];
        #pragma unroll 4
        for (int k = 0; k < HIDD; k++) s += p[k] * c1W[k * 64 + t];
        hid[t] = fmaxf(s, 0.f);
    }
    __syncthreads();
    if (t < 3) {
        float s = c2b[t];
        #pragma unroll 4
        for (int k = 0; k < 64; k++) s += hid[k] * c2W[k * 3 + t];
        lg[t] = s;
        out[g * NCC + t] = s;
    }
    __syncthreads();
    if (t < 3) {
        float mx = fmaxf(fmaxf(lg[0], lg[1]), lg[2]);
        float e0 = expf(lg[0] - mx), e1 = expf(lg[1] - mx), e2 = expf(lg[2] - mx);
        float ev = (t == 0) ? e0 : ((t == 1) ? e1 : e2);
        out[NGG * NCC + NGG * HIDD + g * NCC + t] = ev / (e0 + e1 + e2);
    }
}

// --------------------------------- host --------------------------------
extern "C" void kernel_launch(void* const* d_in, const int* in_sizes, int n_in,
                              void* d_out, int out_size)
{
    const float* x      = (const float*)d_in[0];
    const int*   ei     = (const int*)d_in[1];
    const int*   batch  = (const int*)d_in[2];
    const float* memory = (const float*)d_in[3];
    const float* enc_W  = (const float*)d_in[4];
    const float* enc_b  = (const float*)d_in[5];
    const float* gat_W  = (const float*)d_in[6];
    const float* att_s  = (const float*)d_in[7];
    const float* att_d  = (const float*)d_in[8];
    const float* gat_b  = (const float*)d_in[9];
    const float* W_ih   = (const float*)d_in[10];
    const float* W_hh   = (const float*)d_in[11];
    const float* b_ih   = (const float*)d_in[12];
    const float* b_hh   = (const float*)d_in[13];
    const float* c1W    = (const float*)d_in[14];
    const float* c1b    = (const float*)d_in[15];
    const float* c2W    = (const float*)d_in[16];
    const float* c2b    = (const float*)d_in[17];
    float* out = (float*)d_out;

    float *p_h, *p_z, *p_as, *p_ad, *p_q, *p_gi, *p_gh, *p_pool, *p_cnt;
    int *p_deg, *p_off, *p_cur, *p_esrc;
    __nv_bfloat16 *p_bhi, *p_blo;
    cudaGetSymbolAddress((void**)&p_h,    g_h);
    cudaGetSymbolAddress((void**)&p_z,    g_z);
    cudaGetSymbolAddress((void**)&p_as,   g_as);
    cudaGetSymbolAddress((void**)&p_ad,   g_ad);
    cudaGetSymbolAddress((void**)&p_q,    g_q);
    cudaGetSymbolAddress((void**)&p_gi,   g_gi);
    cudaGetSymbolAddress((void**)&p_gh,   g_gh);
    cudaGetSymbolAddress((void**)&p_pool, g_pool);
    cudaGetSymbolAddress((void**)&p_cnt,  g_cnt);
    cudaGetSymbolAddress((void**)&p_deg,  g_deg);
    cudaGetSymbolAddress((void**)&p_off,  g_off);
    cudaGetSymbolAddress((void**)&p_cur,  g_cur);
    cudaGetSymbolAddress((void**)&p_esrc, g_esrc);
    cudaGetSymbolAddress((void**)&p_bhi,  g_bhi);
    cudaGetSymbolAddress((void**)&p_blo,  g_blo);

    const int MB = (NN + 127) / 128;   // 391

    // CSR build (reused across layers)
    cudaMemsetAsync(p_deg, 0, sizeof(int) * NN);
    cudaMemsetAsync(p_cur, 0, sizeof(int) * NN);
    csr_count<<<(ETOT + 255) / 256, 256>>>(ei, p_deg);
    csr_scan<<<1, 1024>>>(p_deg, p_off);
    csr_scatter<<<(ETOT + 255) / 256, 256>>>(ei, p_off, p_cur, p_esrc);

    // encoder: h = relu(x @ enc_W + enc_b)
    conv_trans128<<<(128 * 128 + 255) / 256, 256>>>(enc_W, p_bhi, p_blo);
    gemm_mma<<<dim3(1, MB), 256>>>(x, p_bhi, p_blo, enc_b, p_h, NN, 128, 128, 1.f, 1);

    for (int l = 0; l < NLL; l++) {
        const float* Wl = gat_W + (size_t)l * HIDD * NHH * HIDD;
        build_q<<<(2048 * 32 + 255) / 256, 256>>>(
            Wl, att_s + l * NHH * HIDD, att_d + l * NHH * HIDD, p_q);
        alpha2<<<(NN * 32 + 255) / 256, 256>>>(p_h, p_q, p_as, p_ad);
        conv_wl<<<(128 * 1024 + 255) / 256, 256>>>(Wl, p_bhi, p_blo);
        edge_agg<<<NN, 128>>>(p_off, p_esrc, p_as, p_ad, p_h, p_z);
        gemm_mma<<<dim3(1, MB), 256>>>(p_z, p_bhi, p_blo, gat_b + l * HIDD, p_h,
                                       NN, 1024, 128, 0.125f, (l < NLL - 1) ? 1 : 0);
    }

    // GRU gates
    conv_pass<<<(384 * 128 + 255) / 256, 256>>>(W_ih, p_bhi, p_blo, 384 * 128);
    gemm_mma<<<dim3(3, MB), 256>>>(p_h, p_bhi, p_blo, b_ih, p_gi, NN, 128, 384, 1.f, 0);
    conv_pass<<<(384 * 128 + 255) / 256, 256>>>(W_hh, p_bhi, p_blo, 384 * 128);
    gemm_mma<<<dim3(3, MB), 256>>>(memory, p_bhi, p_blo, b_hh, p_gh, NN, 128, 384, 1.f, 0);
    gru_kernel<<<((size_t)NN * HIDD + 255) / 256, 256>>>(p_gi, p_gh, memory, p_h);

    // pooling + classifier
    cudaMemsetAsync(p_pool, 0, sizeof(float) * NGG * HIDD);
    cudaMemsetAsync(p_cnt,  0, sizeof(float) * NGG);
    pool_kernel<<<(NN + 499) / 500, 128>>>(p_h, batch, p_pool, p_cnt);
    classifier_kernel<<<NGG, HIDD>>>(p_pool, p_cnt, c1W, c1b, c2W, c2b, out);
}

// round 15
// speedup vs baseline: 1.0016x; 1.0016x over previous
#include <cuda_runtime.h>
#include <cuda_bf16.h>
#include <stdint.h>
#include <math.h>

#define NN   50000
#define EE   800000
#define ETOT (EE + NN)
#define HIDD 128
#define NHH  8
#define NLL  3
#define NGG  64
#define NCC  3

// ---------------- scratch (static device globals) ----------------
__device__ float g_h [(size_t)NN*HIDD];
__device__ float g_z [(size_t)NN*NHH*HIDD];
__device__ float g_as[(size_t)NN*NHH];
__device__ float g_ad[(size_t)NN*NHH];
__device__ float g_q [16*HIDD];
__device__ float g_gi[(size_t)NN*3*HIDD];
__device__ float g_gh[(size_t)NN*3*HIDD];
__device__ float g_pool[NGG*HIDD];
__device__ float g_cnt [NGG];
__device__ int   g_deg [NN];
__device__ int   g_off [NN+1];
__device__ int   g_cur [NN];
__device__ int   g_esrc[ETOT];
__device__ __nv_bfloat16 g_bhi[128*1024];
__device__ __nv_bfloat16 g_blo[128*1024];

// ---------------- mma/ldmatrix helpers (baseline PTX, sm_80+) ----------
__device__ __forceinline__ uint32_t smem_u32(const void* p) {
    uint32_t a;
    asm("{ .reg .u64 t; cvta.to.shared.u64 t, %1; cvt.u32.u64 %0, t; }" : "=r"(a) : "l"(p));
    return a;
}
__device__ __forceinline__ void ldm4(uint32_t* r, uint32_t addr) {
    asm volatile("ldmatrix.sync.aligned.m8n8.x4.shared.b16 {%0,%1,%2,%3}, [%4];"
        : "=r"(r[0]), "=r"(r[1]), "=r"(r[2]), "=r"(r[3]) : "r"(addr));
}
__device__ __forceinline__ void mma16816(float* c, const uint32_t* a, const uint32_t* b) {
    asm volatile("mma.sync.aligned.m16n8k16.row.col.f32.bf16.bf16.f32 "
        "{%0,%1,%2,%3}, {%4,%5,%6,%7}, {%8,%9}, {%0,%1,%2,%3};"
        : "+f"(c[0]), "+f"(c[1]), "+f"(c[2]), "+f"(c[3])
        : "r"(a[0]), "r"(a[1]), "r"(a[2]), "r"(a[3]), "r"(b[0]), "r"(b[1]));
}
__device__ __forceinline__ unsigned pk(__nv_bfloat16 a, __nv_bfloat16 b) {
    unsigned short ua = *(unsigned short*)&a, ub = *(unsigned short*)&b;
    return (unsigned)ua | ((unsigned)ub << 16);
}

// ---------------- tensor-core GEMM via mma.sync -------------------------
// C[M,Nout] = relu?( scale * (A[M,K] @ B^T) + bias ), B[Nout,K] pre-split bf16.
// fp32 emulation: virtual K' = 3K with A' = [Ahi|Ahi|Alo], B' = [Bhi|Blo|Bhi].
// Block 128x128, BK=32, 256 threads (8 warps: 4M x 2N), warp tile 32x64.
#define SMS 40   // smem row stride (bf16 elems): 80B, conflict-free ldmatrix
__global__ __launch_bounds__(256) void gemm_mma(
    const float* __restrict__ A,
    const __nv_bfloat16* __restrict__ Bhi, const __nv_bfloat16* __restrict__ Blo,
    const float* __restrict__ bias, float* __restrict__ C,
    int M, int K, int Nout, float scale, int relu)
{
    __shared__ __align__(16) __nv_bfloat16 As[128 * SMS];
    __shared__ __align__(16) __nv_bfloat16 Bs[128 * SMS];
    const int tid = threadIdx.x;
    const int wid = tid >> 5, lane = tid & 31;
    const int m0 = blockIdx.y * 128;
    const int n0 = blockIdx.x * 128;
    const int Mbase = (wid >> 1) * 32;
    const int Nbase = (wid & 1) * 64;
    const uint32_t smA = smem_u32(As), smB = smem_u32(Bs);

    float acc[2][8][4];
    #pragma unroll
    for (int i = 0; i < 2; i++)
        #pragma unroll
        for (int j = 0; j < 8; j++)
            #pragma unroll
            for (int k = 0; k < 4; k++) acc[i][j][k] = 0.f;

    const int lrow = tid >> 1;              // loader row 0..127
    const int lcol = (tid & 1) * 16;        // col half
    const bool avalid = (m0 + lrow) < M;
    const int nckpt = K >> 5;

    for (int term = 0; term < 3; term++) {
        const bool alo = (term == 2);
        const __nv_bfloat16* Bsrc = (term == 1) ? Blo : Bhi;
        for (int c = 0; c < nckpt; c++) {
            const int kc = c << 5;
            // stage A: 128x32 f32 -> bf16 (hi or lo part)
            {
                const float4* ap = (const float4*)(A + (size_t)(m0 + lrow) * K + kc + lcol);
                #pragma unroll
                for (int j = 0; j < 4; j++) {
                    float4 v = avalid ? ap[j] : make_float4(0.f, 0.f, 0.f, 0.f);
                    __nv_bfloat16 hx = __float2bfloat16(v.x), hy = __float2bfloat16(v.y);
                    __nv_bfloat16 hz = __float2bfloat16(v.z), hw = __float2bfloat16(v.w);
                    unsigned u0, u1;
                    if (!alo) { u0 = pk(hx, hy); u1 = pk(hz, hw); }
                    else {
                        u0 = pk(__float2bfloat16(v.x - __bfloat162float(hx)),
                                __float2bfloat16(v.y - __bfloat162float(hy)));
                        u1 = pk(__float2bfloat16(v.z - __bfloat162float(hz)),
                                __float2bfloat16(v.w - __bfloat162float(hw)));
                    }
                    uint2 st; st.x = u0; st.y = u1;
                    *(uint2*)&As[lrow * SMS + lcol + j * 4] = st;
                }
            }
            // stage B: 128x32 bf16
            {
                const uint4* bp = (const uint4*)(Bsrc + (size_t)(n0 + lrow) * K + kc + lcol);
                #pragma unroll
                for (int j = 0; j < 2; j++)
                    *(uint4*)&Bs[lrow * SMS + lcol + j * 8] = bp[j];
            }
            __syncthreads();

            #pragma unroll
            for (int k16o = 0; k16o < 32; k16o += 16) {
                uint32_t afr[2][4], bfr[8][2];
                #pragma unroll
                for (int mi = 0; mi < 2; mi++) {
                    int row = Mbase + mi * 16 + (lane & 15);
                    int col = k16o + ((lane >> 4) << 3);
                    ldm4(afr[mi], smA + (uint32_t)(row * SMS + col) * 2);
                }
                #pragma unroll
                for (int p = 0; p < 4; p++) {
                    int grp = lane >> 3;
                    int n = Nbase + p * 16 + ((grp >> 1) << 3) + (lane & 7);
                    int k = k16o + ((grp & 1) << 3);
                    uint32_t r[4];
                    ldm4(r, smB + (uint32_t)(n * SMS + k) * 2);
                    bfr[2 * p][0] = r[0]; bfr[2 * p][1] = r[1];
                    bfr[2 * p + 1][0] = r[2]; bfr[2 * p + 1][1] = r[3];
                }
                #pragma unroll
                for (int mi = 0; mi < 2; mi++)
                    #pragma unroll
                    for (int ni = 0; ni < 8; ni++)
                        mma16816(acc[mi][ni], afr[mi], bfr[ni]);
            }
            __syncthreads();
        }
    }

    // epilogue: c0,c1 -> (row, col..col+1); c2,c3 -> (row+8, ...)
    #pragma unroll
    for (int mi = 0; mi < 2; mi++) {
        int r0 = m0 + Mbase + mi * 16 + (lane >> 2);
        #pragma unroll
        for (int rr = 0; rr < 2; rr++) {
            int row = r0 + rr * 8;
            if (row >= M) continue;
            #pragma unroll
            for (int ni = 0; ni < 8; ni++) {
                int col = n0 + Nbase + ni * 8 + (lane & 3) * 2;
                float v0 = acc[mi][ni][rr * 2 + 0] * scale + (bias ? bias[col]     : 0.f);
                float v1 = acc[mi][ni][rr * 2 + 1] * scale + (bias ? bias[col + 1] : 0.f);
                if (relu) { v0 = fmaxf(v0, 0.f); v1 = fmaxf(v1, 0.f); }
                float2 o; o.x = v0; o.y = v1;
                *(float2*)(C + (size_t)row * Nout + col) = o;
            }
        }
    }
}

// ---------------- weight pre-split kernels ------------------------------
__global__ void conv_trans128(const float* __restrict__ src,
                              __nv_bfloat16* __restrict__ hi, __nv_bfloat16* __restrict__ lo)
{
    int i = blockIdx.x * blockDim.x + threadIdx.x;
    if (i >= 128 * 128) return;
    float v = src[(i & 127) * 128 + (i >> 7)];
    __nv_bfloat16 h = __float2bfloat16(v);
    hi[i] = h; lo[i] = __float2bfloat16(v - __bfloat162float(h));
}
// B[cout][h*128+k] = W[k][h*128+cout]
__global__ void conv_wl(const float* __restrict__ W,
                        __nv_bfloat16* __restrict__ hi, __nv_bfloat16* __restrict__ lo)
{
    int i = blockIdx.x * blockDim.x + threadIdx.x;
    if (i >= 128 * 1024) return;
    float v = W[(size_t)(i & 127) * 1024 + (((i >> 7) & 7) * 128) + (i >> 10)];
    __nv_bfloat16 h = __float2bfloat16(v);
    hi[i] = h; lo[i] = __float2bfloat16(v - __bfloat162float(h));
}
__global__ void conv_pass(const float* __restrict__ src,
                          __nv_bfloat16* __restrict__ hi, __nv_bfloat16* __restrict__ lo, int n)
{
    int i = blockIdx.x * blockDim.x + threadIdx.x;
    if (i >= n) return;
    float v = src[i];
    __nv_bfloat16 h = __float2bfloat16(v);
    hi[i] = h; lo[i] = __float2bfloat16(v - __bfloat162float(h));
}

// ---------------- CSR build ----------------
__global__ void csr_count(const int* __restrict__ ei, int* __restrict__ deg)
{
    int e = blockIdx.x * blockDim.x + threadIdx.x;
    if (e >= ETOT) return;
    int d = (e < EE) ? ei[EE + e] : (e - EE);
    atomicAdd(&deg[d], 1);
}
__global__ __launch_bounds__(1024) void csr_scan(const int* __restrict__ deg,
                                                 int* __restrict__ off)
{
    const int CHK = (NN + 1023) / 1024;
    int t = threadIdx.x;
    int lo = t * CHK, hi = min(lo + CHK, NN);
    int s = 0;
    for (int i = lo; i < hi; i++) s += deg[i];
    __shared__ int ps[1024];
    ps[t] = s; __syncthreads();
    for (int o = 1; o < 1024; o <<= 1) {
        int v = (t >= o) ? ps[t - o] : 0;
        __syncthreads();
        ps[t] += v;
        __syncthreads();
    }
    int run = (t > 0) ? ps[t - 1] : 0;
    for (int i = lo; i < hi; i++) { off[i] = run; run += deg[i]; }
    if (t == 1023) off[NN] = run;
}
__global__ void csr_scatter(const int* __restrict__ ei, const int* __restrict__ off,
                            int* __restrict__ cur, int* __restrict__ esrc)
{
    int e = blockIdx.x * blockDim.x + threadIdx.x;
    if (e >= ETOT) return;
    int s, d;
    if (e < EE) { s = ei[e]; d = ei[EE + e]; }
    else        { s = e - EE; d = s; }
    int p = atomicAdd(&cur[d], 1);
    esrc[off[d] + p] = s;
}

// ---------------- attention projections ----------------
__global__ void build_q(const float* __restrict__ W, const float* __restrict__ asrc,
                        const float* __restrict__ adst, float* __restrict__ qT)
{
    int w = (blockIdx.x * blockDim.x + threadIdx.x) >> 5;
    int lane = threadIdx.x & 31;
    if (w >= 2048) return;
    int j = w >> 7, k = w & 127;
    int h = j & 7;
    const float* att = ((j < 8) ? asrc : adst) + h * HIDD;
    const float* wr = W + (size_t)k * (NHH * HIDD) + h * HIDD;
    float4 a = *(const float4*)(wr + lane * 4);
    float4 b = *(const float4*)(att + lane * 4);
    float s = a.x*b.x + a.y*b.y + a.z*b.z + a.w*b.w;
    #pragma unroll
    for (int o = 16; o; o >>= 1) s += __shfl_xor_sync(0xffffffffu, s, o);
    if (lane == 0) qT[j * HIDD + k] = s;
}

__global__ __launch_bounds__(256) void alpha2(const float* __restrict__ hf,
                                              const float* __restrict__ qT,
                                              float* __restrict__ as_, float* __restrict__ ad_)
{
    __shared__ float qs[16][HIDD];
    int t = threadIdx.x;
    for (int i = t; i < 16 * HIDD; i += 256) qs[i >> 7][i & 127] = qT[i];
    __syncthreads();
    int n = (blockIdx.x * 256 + t) >> 5;
    int lane = t & 31;
    if (n >= NN) return;
    float4 hv = *(const float4*)(hf + (size_t)n * HIDD + lane * 4);
    #pragma unroll
    for (int j = 0; j < 16; j++) {
        float4 qv = *(const float4*)&qs[j][lane * 4];
        float s = hv.x*qv.x + hv.y*qv.y + hv.z*qv.z + hv.w*qv.w;
        #pragma unroll
        for (int o = 16; o; o >>= 1) s += __shfl_xor_sync(0xffffffffu, s, o);
        if (lane == 0) {
            if (j < 8) as_[(size_t)n * 8 + j] = s;
            else       ad_[(size_t)n * 8 + (j - 8)] = s;
        }
    }
}

// ---------------- CSR edge aggregation ----------------
__global__ __launch_bounds__(128) void edge_agg(
    const int* __restrict__ off, const int* __restrict__ esrc,
    const float* __restrict__ as_, const float* __restrict__ ad_,
    const float* __restrict__ hf, float* __restrict__ zb)
{
    int n = blockIdx.x, t = threadIdx.x, h = t & 7;
    int e0 = off[n], e1 = off[n + 1];
    __shared__ float adn[8];
    __shared__ float den[8];
    __shared__ float red[16][8];
    __shared__ float ws[32][8];
    __shared__ int   ssm[32];
    if (t < 8) adn[t] = ad_[(size_t)n * 8 + t];
    __syncthreads();

    float part = 0.f;
    for (int i = e0 + (t >> 3); i < e1; i += 16) {
        int s = esrc[i];
        float v = as_[(size_t)s * 8 + h] + adn[h];
        v = v > 0.f ? v : 0.2f * v;
        part += __expf(v);
    }
    red[t >> 3][h] = part;
    __syncthreads();
    if (t < 8) {
        float x = 0.f;
        #pragma unroll
        for (int i = 0; i < 16; i++) x += red[i][t];
        den[t] = x;
    }
    __syncthreads();

    float z[8];
    #pragma unroll
    for (int i = 0; i < 8; i++) z[i] = 0.f;

    for (int c0 = e0; c0 < e1; c0 += 32) {
        int m = min(32, e1 - c0);
        for (int i = t >> 3; i < m; i += 16) {
            int s = esrc[c0 + i];
            if (h == 0) ssm[i] = s;
            float v = as_[(size_t)s * 8 + h] + adn[h];
            v = v > 0.f ? v : 0.2f * v;
            ws[i][h] = __expf(v) / (den[h] + 1e-16f);
        }
        __syncthreads();
        for (int i = 0; i < m; i++) {
            float val = hf[(size_t)ssm[i] * HIDD + t];
            #pragma unroll
            for (int hh = 0; hh < 8; hh++) z[hh] += ws[i][hh] * val;
        }
        __syncthreads();
    }
    float* zr = zb + (size_t)n * (NHH * HIDD) + t;
    #pragma unroll
    for (int hh = 0; hh < 8; hh++) zr[hh * HIDD] = z[hh];
}

// ---------------- GRU / pool / classifier ----------------
__global__ void gru_kernel(const float* __restrict__ gi, const float* __restrict__ gh,
                           const float* __restrict__ mem, float* __restrict__ hout)
{
    size_t i = (size_t)blockIdx.x * blockDim.x + threadIdx.x;
    if (i >= (size_t)NN * HIDD) return;
    size_t n = i >> 7; int c = (int)(i & 127);
    const float* a = gi + n * 384;
    const float* b = gh + n * 384;
    float r  = 1.f / (1.f + __expf(-(a[c]       + b[c])));
    float z  = 1.f / (1.f + __expf(-(a[128 + c] + b[128 + c])));
    float nc = tanhf(a[256 + c] + r * b[256 + c]);
    hout[i] = (1.f - z) * nc + z * mem[i];
}

__global__ void pool_kernel(const float* __restrict__ h, const int* __restrict__ batch,
                            float* __restrict__ sums, float* __restrict__ cnt)
{
    const int CHUNK = 500;
    int start = blockIdx.x * CHUNK;
    if (start >= NN) return;
    int end = min(start + CHUNK, NN);
    int c = threadIdx.x;
    int g = batch[start];
    float acc = 0.f, count = 0.f;
    for (int n = start; n < end; n++) {
        int bg = batch[n];
        if (bg != g) {
            atomicAdd(&sums[g * HIDD + c], acc);
            if (c == 0) atomicAdd(&cnt[g], count);
            acc = 0.f; count = 0.f; g = bg;
        }
        acc += h[(size_t)n * HIDD + c];
        count += 1.f;
    }
    atomicAdd(&sums[g * HIDD + c], acc);
    if (c == 0) atomicAdd(&cnt[g], count);
}

__global__ void classifier_kernel(const float* __restrict__ sums, const float* __restrict__ cnt,
                                  const float* __restrict__ c1W, const float* __restrict__ c1b,
                                  const float* __restrict__ c2W, const float* __restrict__ c2b,
                                  float* __restrict__ out)
{
    __shared__ float p[HIDD];
    __shared__ float hid[64];
    __shared__ float lg[3];
    int g = blockIdx.x, t = threadIdx.x;
    float c = fmaxf(cnt[g], 1.f);
    float pv = sums[g * HIDD + t] / c;
    p[t] = pv;
    out[NGG * NCC + g * HIDD + t] = pv;
    __syncthreads();
    if (t < 64) {
        float s = c1b[t];
        #pragma unroll 4
        for (int k = 0; k < HIDD; k++) s += p[k] * c1W[k * 64 + t];
        hid[t] = fmaxf(s, 0.f);
    }
    __syncthreads();
    if (t < 3) {
        float s = c2b[t];
        #pragma unroll 4
        for (int k = 0; k < 64; k++) s += hid[k] * c2W[k * 3 + t];
        lg[t] = s;
        out[g * NCC + t] = s;
    }
    __syncthreads();
    if (t < 3) {
        float mx = fmaxf(fmaxf(lg[0], lg[1]), lg[2]);
        float e0 = expf(lg[0] - mx), e1 = expf(lg[1] - mx), e2 = expf(lg[2] - mx);
        float ev = (t == 0) ? e0 : ((t == 1) ? e1 : e2);
        out[NGG * NCC + NGG * HIDD + g * NCC + t] = ev / (e0 + e1 + e2);
    }
}

// --------------------------------- host --------------------------------
extern "C" void kernel_launch(void* const* d_in, const int* in_sizes, int n_in,
                              void* d_out, int out_size)
{
    const float* x      = (const float*)d_in[0];
    const int*   ei     = (const int*)d_in[1];
    const int*   batch  = (const int*)d_in[2];
    const float* memory = (const float*)d_in[3];
    const float* enc_W  = (const float*)d_in[4];
    const float* enc_b  = (const float*)d_in[5];
    const float* gat_W  = (const float*)d_in[6];
    const float* att_s  = (const float*)d_in[7];
    const float* att_d  = (const float*)d_in[8];
    const float* gat_b  = (const float*)d_in[9];
    const float* W_ih   = (const float*)d_in[10];
    const float* W_hh   = (const float*)d_in[11];
    const float* b_ih   = (const float*)d_in[12];
    const float* b_hh   = (const float*)d_in[13];
    const float* c1W    = (const float*)d_in[14];
    const float* c1b    = (const float*)d_in[15];
    const float* c2W    = (const float*)d_in[16];
    const float* c2b    = (const float*)d_in[17];
    float* out = (float*)d_out;

    float *p_h, *p_z, *p_as, *p_ad, *p_q, *p_gi, *p_gh, *p_pool, *p_cnt;
    int *p_deg, *p_off, *p_cur, *p_esrc;
    __nv_bfloat16 *p_bhi, *p_blo;
    cudaGetSymbolAddress((void**)&p_h,    g_h);
    cudaGetSymbolAddress((void**)&p_z,    g_z);
    cudaGetSymbolAddress((void**)&p_as,   g_as);
    cudaGetSymbolAddress((void**)&p_ad,   g_ad);
    cudaGetSymbolAddress((void**)&p_q,    g_q);
    cudaGetSymbolAddress((void**)&p_gi,   g_gi);
    cudaGetSymbolAddress((void**)&p_gh,   g_gh);
    cudaGetSymbolAddress((void**)&p_pool, g_pool);
    cudaGetSymbolAddress((void**)&p_cnt,  g_cnt);
    cudaGetSymbolAddress((void**)&p_deg,  g_deg);
    cudaGetSymbolAddress((void**)&p_off,  g_off);
    cudaGetSymbolAddress((void**)&p_cur,  g_cur);
    cudaGetSymbolAddress((void**)&p_esrc, g_esrc);
    cudaGetSymbolAddress((void**)&p_bhi,  g_bhi);
    cudaGetSymbolAddress((void**)&p_blo,  g_blo);

    const int MB = (NN + 127) / 128;   // 391

    // CSR build (reused across layers)
    cudaMemsetAsync(p_deg, 0, sizeof(int) * NN);
    cudaMemsetAsync(p_cur, 0, sizeof(int) * NN);
    csr_count<<<(ETOT + 255) / 256, 256>>>(ei, p_deg);
    csr_scan<<<1, 1024>>>(p_deg, p_off);
    csr_scatter<<<(ETOT + 255) / 256, 256>>>(ei, p_off, p_cur, p_esrc);

    // encoder: h = relu(x @ enc_W + enc_b)
    conv_trans128<<<(128 * 128 + 255) / 256, 256>>>(enc_W, p_bhi, p_blo);
    gemm_mma<<<dim3(1, MB), 256>>>(x, p_bhi, p_blo, enc_b, p_h, NN, 128, 128, 1.f, 1);

    for (int l = 0; l < NLL; l++) {
        const float* Wl = gat_W + (size_t)l * HIDD * NHH * HIDD;
        build_q<<<(2048 * 32 + 255) / 256, 256>>>(
            Wl, att_s + l * NHH * HIDD, att_d + l * NHH * HIDD, p_q);
        alpha2<<<(NN * 32 + 255) / 256, 256>>>(p_h, p_q, p_as, p_ad);
        conv_wl<<<(128 * 1024 + 255) / 256, 256>>>(Wl, p_bhi, p_blo);
        edge_agg<<<NN, 128>>>(p_off, p_esrc, p_as, p_ad, p_h, p_z);
        gemm_mma<<<dim3(1, MB), 256>>>(p_z, p_bhi, p_blo, gat_b + l * HIDD, p_h,
                                       NN, 1024, 128, 0.125f, (l < NLL - 1) ? 1 : 0);
    }

    // GRU gates
    conv_pass<<<(384 * 128 + 255) / 256, 256>>>(W_ih, p_bhi, p_blo, 384 * 128);
    gemm_mma<<<dim3(3, MB), 256>>>(p_h, p_bhi, p_blo, b_ih, p_gi, NN, 128, 384, 1.f, 0);
    conv_pass<<<(384 * 128 + 255) / 256, 256>>>(W_hh, p_bhi, p_blo, 384 * 128);
    gemm_mma<<<dim3(3, MB), 256>>>(memory, p_bhi, p_blo, b_hh, p_gh, NN, 128, 384, 1.f, 0);
    gru_kernel<<<((size_t)NN * HIDD + 255) / 256, 256>>>(p_gi, p_gh, memory, p_h);

    // pooling + classifier
    cudaMemsetAsync(p_pool, 0, sizeof(float) * NGG * HIDD);
    cudaMemsetAsync(p_cnt,  0, sizeof(float) * NGG);
    pool_kernel<<<(NN + 499) / 500, 128>>>(p_h, batch, p_pool, p_cnt);
    classifier_kernel<<<NGG, HIDD>>>(p_pool, p_cnt, c1W, c1b, c2W, c2b, out);
}

// round 16
// speedup vs baseline: 1.0025x; 1.0009x over previous
#include <cuda_runtime.h>
#include <cuda_bf16.h>
#include <stdint.h>
#include <math.h>

#define NN   50000
#define EE   800000
#define ETOT (EE + NN)
#define HIDD 128
#define NHH  8
#define NLL  3
#define NGG  64
#define NCC  3

// ---------------- scratch (static device globals) ----------------
__device__ float g_h [(size_t)NN*HIDD];
__device__ float g_z [(size_t)NN*NHH*HIDD];
__device__ float g_as[(size_t)NN*NHH];
__device__ float g_ad[(size_t)NN*NHH];
__device__ float g_q [16*HIDD];
__device__ float g_gi[(size_t)NN*3*HIDD];
__device__ float g_gh[(size_t)NN*3*HIDD];
__device__ float g_pool[NGG*HIDD];
__device__ float g_cnt [NGG];
__device__ int   g_deg [NN];
__device__ int   g_off [NN+1];
__device__ int   g_cur [NN];
__device__ int   g_esrc[ETOT];
__device__ __nv_bfloat16 g_bhi[128*1024];
__device__ __nv_bfloat16 g_blo[128*1024];

// ---------------- mma/ldmatrix helpers (baseline PTX, sm_80+) ----------
__device__ __forceinline__ uint32_t smem_u32(const void* p) {
    uint32_t a;
    asm("{ .reg .u64 t; cvta.to.shared.u64 t, %1; cvt.u32.u64 %0, t; }" : "=r"(a) : "l"(p));
    return a;
}
__device__ __forceinline__ void ldm4(uint32_t* r, uint32_t addr) {
    asm volatile("ldmatrix.sync.aligned.m8n8.x4.shared.b16 {%0,%1,%2,%3}, [%4];"
        : "=r"(r[0]), "=r"(r[1]), "=r"(r[2]), "=r"(r[3]) : "r"(addr));
}
__device__ __forceinline__ void mma16816(float* c, const uint32_t* a, const uint32_t* b) {
    asm volatile("mma.sync.aligned.m16n8k16.row.col.f32.bf16.bf16.f32 "
        "{%0,%1,%2,%3}, {%4,%5,%6,%7}, {%8,%9}, {%0,%1,%2,%3};"
        : "+f"(c[0]), "+f"(c[1]), "+f"(c[2]), "+f"(c[3])
        : "r"(a[0]), "r"(a[1]), "r"(a[2]), "r"(a[3]), "r"(b[0]), "r"(b[1]));
}
__device__ __forceinline__ unsigned pk(__nv_bfloat16 a, __nv_bfloat16 b) {
    unsigned short ua = *(unsigned short*)&a, ub = *(unsigned short*)&b;
    return (unsigned)ua | ((unsigned)ub << 16);
}

// ---------------- tensor-core GEMM via mma.sync -------------------------
// C[M,Nout] = relu?( scale * (A[M,K] @ B^T) + bias ), B[Nout,K] pre-split bf16.
// fp32 emulation: virtual K' = 3K with A' = [Ahi|Ahi|Alo], B' = [Bhi|Blo|Bhi].
// Block 128x128, BK=32, 256 threads (8 warps: 4M x 2N), warp tile 32x64.
#define SMS 40   // smem row stride (bf16 elems): 80B, conflict-free ldmatrix
__global__ __launch_bounds__(256) void gemm_mma(
    const float* __restrict__ A,
    const __nv_bfloat16* __restrict__ Bhi, const __nv_bfloat16* __restrict__ Blo,
    const float* __restrict__ bias, float* __restrict__ C,
    int M, int K, int Nout, float scale, int relu)
{
    __shared__ __align__(16) __nv_bfloat16 As[128 * SMS];
    __shared__ __align__(16) __nv_bfloat16 Bs[128 * SMS];
    const int tid = threadIdx.x;
    const int wid = tid >> 5, lane = tid & 31;
    const int m0 = blockIdx.y * 128;
    const int n0 = blockIdx.x * 128;
    const int Mbase = (wid >> 1) * 32;
    const int Nbase = (wid & 1) * 64;
    const uint32_t smA = smem_u32(As), smB = smem_u32(Bs);

    float acc[2][8][4];
    #pragma unroll
    for (int i = 0; i < 2; i++)
        #pragma unroll
        for (int j = 0; j < 8; j++)
            #pragma unroll
            for (int k = 0; k < 4; k++) acc[i][j][k] = 0.f;

    const int lrow = tid >> 1;              // loader row 0..127
    const int lcol = (tid & 1) * 16;        // col half
    const bool avalid = (m0 + lrow) < M;
    const int nckpt = K >> 5;

    for (int term = 0; term < 3; term++) {
        const bool alo = (term == 2);
        const __nv_bfloat16* Bsrc = (term == 1) ? Blo : Bhi;
        for (int c = 0; c < nckpt; c++) {
            const int kc = c << 5;
            // stage A: 128x32 f32 -> bf16 (hi or lo part)
            {
                const float4* ap = (const float4*)(A + (size_t)(m0 + lrow) * K + kc + lcol);
                #pragma unroll
                for (int j = 0; j < 4; j++) {
                    float4 v = avalid ? ap[j] : make_float4(0.f, 0.f, 0.f, 0.f);
                    __nv_bfloat16 hx = __float2bfloat16(v.x), hy = __float2bfloat16(v.y);
                    __nv_bfloat16 hz = __float2bfloat16(v.z), hw = __float2bfloat16(v.w);
                    unsigned u0, u1;
                    if (!alo) { u0 = pk(hx, hy); u1 = pk(hz, hw); }
                    else {
                        u0 = pk(__float2bfloat16(v.x - __bfloat162float(hx)),
                                __float2bfloat16(v.y - __bfloat162float(hy)));
                        u1 = pk(__float2bfloat16(v.z - __bfloat162float(hz)),
                                __float2bfloat16(v.w - __bfloat162float(hw)));
                    }
                    uint2 st; st.x = u0; st.y = u1;
                    *(uint2*)&As[lrow * SMS + lcol + j * 4] = st;
                }
            }
            // stage B: 128x32 bf16
            {
                const uint4* bp = (const uint4*)(Bsrc + (size_t)(n0 + lrow) * K + kc + lcol);
                #pragma unroll
                for (int j = 0; j < 2; j++)
                    *(uint4*)&Bs[lrow * SMS + lcol + j * 8] = bp[j];
            }
            __syncthreads();

            #pragma unroll
            for (int k16o = 0; k16o < 32; k16o += 16) {
                uint32_t afr[2][4], bfr[8][2];
                #pragma unroll
                for (int mi = 0; mi < 2; mi++) {
                    int row = Mbase + mi * 16 + (lane & 15);
                    int col = k16o + ((lane >> 4) << 3);
                    ldm4(afr[mi], smA + (uint32_t)(row * SMS + col) * 2);
                }
                #pragma unroll
                for (int p = 0; p < 4; p++) {
                    int grp = lane >> 3;
                    int n = Nbase + p * 16 + ((grp >> 1) << 3) + (lane & 7);
                    int k = k16o + ((grp & 1) << 3);
                    uint32_t r[4];
                    ldm4(r, smB + (uint32_t)(n * SMS + k) * 2);
                    bfr[2 * p][0] = r[0]; bfr[2 * p][1] = r[1];
                    bfr[2 * p + 1][0] = r[2]; bfr[2 * p + 1][1] = r[3];
                }
                #pragma unroll
                for (int mi = 0; mi < 2; mi++)
                    #pragma unroll
                    for (int ni = 0; ni < 8; ni++)
                        mma16816(acc[mi][ni], afr[mi], bfr[ni]);
            }
            __syncthreads();
        }
    }

    // epilogue: c0,c1 -> (row, col..col+1); c2,c3 -> (row+8, ...)
    #pragma unroll
    for (int mi = 0; mi < 2; mi++) {
        int r0 = m0 + Mbase + mi * 16 + (lane >> 2);
        #pragma unroll
        for (int rr = 0; rr < 2; rr++) {
            int row = r0 + rr * 8;
            if (row >= M) continue;
            #pragma unroll
            for (int ni = 0; ni < 8; ni++) {
                int col = n0 + Nbase + ni * 8 + (lane & 3) * 2;
                float v0 = acc[mi][ni][rr * 2 + 0] * scale + (bias ? bias[col]     : 0.f);
                float v1 = acc[mi][ni][rr * 2 + 1] * scale + (bias ? bias[col + 1] : 0.f);
                if (relu) { v0 = fmaxf(v0, 0.f); v1 = fmaxf(v1, 0.f); }
                float2 o; o.x = v0; o.y = v1;
                *(float2*)(C + (size_t)row * Nout + col) = o;
            }
        }
    }
}

// ---------------- weight pre-split kernels ------------------------------
__global__ void conv_trans128(const float* __restrict__ src,
                              __nv_bfloat16* __restrict__ hi, __nv_bfloat16* __restrict__ lo)
{
    int i = blockIdx.x * blockDim.x + threadIdx.x;
    if (i >= 128 * 128) return;
    float v = src[(i & 127) * 128 + (i >> 7)];
    __nv_bfloat16 h = __float2bfloat16(v);
    hi[i] = h; lo[i] = __float2bfloat16(v - __bfloat162float(h));
}
// B[cout][h*128+k] = W[k][h*128+cout]
__global__ void conv_wl(const float* __restrict__ W,
                        __nv_bfloat16* __restrict__ hi, __nv_bfloat16* __restrict__ lo)
{
    int i = blockIdx.x * blockDim.x + threadIdx.x;
    if (i >= 128 * 1024) return;
    float v = W[(size_t)(i & 127) * 1024 + (((i >> 7) & 7) * 128) + (i >> 10)];
    __nv_bfloat16 h = __float2bfloat16(v);
    hi[i] = h; lo[i] = __float2bfloat16(v - __bfloat162float(h));
}
__global__ void conv_pass(const float* __restrict__ src,
                          __nv_bfloat16* __restrict__ hi, __nv_bfloat16* __restrict__ lo, int n)
{
    int i = blockIdx.x * blockDim.x + threadIdx.x;
    if (i >= n) return;
    float v = src[i];
    __nv_bfloat16 h = __float2bfloat16(v);
    hi[i] = h; lo[i] = __float2bfloat16(v - __bfloat162float(h));
}

// ---------------- CSR build ----------------
__global__ void csr_count(const int* __restrict__ ei, int* __restrict__ deg)
{
    int e = blockIdx.x * blockDim.x + threadIdx.x;
    if (e >= ETOT) return;
    int d = (e < EE) ? ei[EE + e] : (e - EE);
    atomicAdd(&deg[d], 1);
}
__global__ __launch_bounds__(1024) void csr_scan(const int* __restrict__ deg,
                                                 int* __restrict__ off)
{
    const int CHK = (NN + 1023) / 1024;
    int t = threadIdx.x;
    int lo = t * CHK, hi = min(lo + CHK, NN);
    int s = 0;
    for (int i = lo; i < hi; i++) s += deg[i];
    __shared__ int ps[1024];
    ps[t] = s; __syncthreads();
    for (int o = 1; o < 1024; o <<= 1) {
        int v = (t >= o) ? ps[t - o] : 0;
        __syncthreads();
        ps[t] += v;
        __syncthreads();
    }
    int run = (t > 0) ? ps[t - 1] : 0;
    for (int i = lo; i < hi; i++) { off[i] = run; run += deg[i]; }
    if (t == 1023) off[NN] = run;
}
__global__ void csr_scatter(const int* __restrict__ ei, const int* __restrict__ off,
                            int* __restrict__ cur, int* __restrict__ esrc)
{
    int e = blockIdx.x * blockDim.x + threadIdx.x;
    if (e >= ETOT) return;
    int s, d;
    if (e < EE) { s = ei[e]; d = ei[EE + e]; }
    else        { s = e - EE; d = s; }
    int p = atomicAdd(&cur[d], 1);
    esrc[off[d] + p] = s;
}

// ---------------- attention projections ----------------
__global__ void build_q(const float* __restrict__ W, const float* __restrict__ asrc,
                        const float* __restrict__ adst, float* __restrict__ qT)
{
    int w = (blockIdx.x * blockDim.x + threadIdx.x) >> 5;
    int lane = threadIdx.x & 31;
    if (w >= 2048) return;
    int j = w >> 7, k = w & 127;
    int h = j & 7;
    const float* att = ((j < 8) ? asrc : adst) + h * HIDD;
    const float* wr = W + (size_t)k * (NHH * HIDD) + h * HIDD;
    float4 a = *(const float4*)(wr + lane * 4);
    float4 b = *(const float4*)(att + lane * 4);
    float s = a.x*b.x + a.y*b.y + a.z*b.z + a.w*b.w;
    #pragma unroll
    for (int o = 16; o; o >>= 1) s += __shfl_xor_sync(0xffffffffu, s, o);
    if (lane == 0) qT[j * HIDD + k] = s;
}

__global__ __launch_bounds__(256) void alpha2(const float* __restrict__ hf,
                                              const float* __restrict__ qT,
                                              float* __restrict__ as_, float* __restrict__ ad_)
{
    __shared__ float qs[16][HIDD];
    int t = threadIdx.x;
    for (int i = t; i < 16 * HIDD; i += 256) qs[i >> 7][i & 127] = qT[i];
    __syncthreads();
    int n = (blockIdx.x * 256 + t) >> 5;
    int lane = t & 31;
    if (n >= NN) return;
    float4 hv = *(const float4*)(hf + (size_t)n * HIDD + lane * 4);
    #pragma unroll
    for (int j = 0; j < 16; j++) {
        float4 qv = *(const float4*)&qs[j][lane * 4];
        float s = hv.x*qv.x + hv.y*qv.y + hv.z*qv.z + hv.w*qv.w;
        #pragma unroll
        for (int o = 16; o; o >>= 1) s += __shfl_xor_sync(0xffffffffu, s, o);
        if (lane == 0) {
            if (j < 8) as_[(size_t)n * 8 + j] = s;
            else       ad_[(size_t)n * 8 + (j - 8)] = s;
        }
    }
}

// ---------------- CSR edge aggregation ----------------
__global__ __launch_bounds__(128) void edge_agg(
    const int* __restrict__ off, const int* __restrict__ esrc,
    const float* __restrict__ as_, const float* __restrict__ ad_,
    const float* __restrict__ hf, float* __restrict__ zb)
{
    int n = blockIdx.x, t = threadIdx.x, h = t & 7;
    int e0 = off[n], e1 = off[n + 1];
    __shared__ float adn[8];
    __shared__ float den[8];
    __shared__ float red[16][8];
    __shared__ float ws[32][8];
    __shared__ int   ssm[32];
    if (t < 8) adn[t] = ad_[(size_t)n * 8 + t];
    __syncthreads();

    float part = 0.f;
    for (int i = e0 + (t >> 3); i < e1; i += 16) {
        int s = esrc[i];
        float v = as_[(size_t)s * 8 + h] + adn[h];
        v = v > 0.f ? v : 0.2f * v;
        part += __expf(v);
    }
    red[t >> 3][h] = part;
    __syncthreads();
    if (t < 8) {
        float x = 0.f;
        #pragma unroll
        for (int i = 0; i < 16; i++) x += red[i][t];
        den[t] = x;
    }
    __syncthreads();

    float z[8];
    #pragma unroll
    for (int i = 0; i < 8; i++) z[i] = 0.f;

    for (int c0 = e0; c0 < e1; c0 += 32) {
        int m = min(32, e1 - c0);
        for (int i = t >> 3; i < m; i += 16) {
            int s = esrc[c0 + i];
            if (h == 0) ssm[i] = s;
            float v = as_[(size_t)s * 8 + h] + adn[h];
            v = v > 0.f ? v : 0.2f * v;
            ws[i][h] = __expf(v) / (den[h] + 1e-16f);
        }
        __syncthreads();
        for (int i = 0; i < m; i++) {
            float val = hf[(size_t)ssm[i] * HIDD + t];
            #pragma unroll
            for (int hh = 0; hh < 8; hh++) z[hh] += ws[i][hh] * val;
        }
        __syncthreads();
    }
    float* zr = zb + (size_t)n * (NHH * HIDD) + t;
    #pragma unroll
    for (int hh = 0; hh < 8; hh++) zr[hh * HIDD] = z[hh];
}

// ---------------- GRU / pool / classifier ----------------
__global__ void gru_kernel(const float* __restrict__ gi, const float* __restrict__ gh,
                           const float* __restrict__ mem, float* __restrict__ hout)
{
    size_t i = (size_t)blockIdx.x * blockDim.x + threadIdx.x;
    if (i >= (size_t)NN * HIDD) return;
    size_t n = i >> 7; int c = (int)(i & 127);
    const float* a = gi + n * 384;
    const float* b = gh + n * 384;
    float r  = 1.f / (1.f + __expf(-(a[c]       + b[c])));
    float z  = 1.f / (1.f + __expf(-(a[128 + c] + b[128 + c])));
    float nc = tanhf(a[256 + c] + r * b[256 + c]);
    hout[i] = (1.f - z) * nc + z * mem[i];
}

__global__ void pool_kernel(const float* __restrict__ h, const int* __restrict__ batch,
                            float* __restrict__ sums, float* __restrict__ cnt)
{
    const int CHUNK = 500;
    int start = blockIdx.x * CHUNK;
    if (start >= NN) return;
    int end = min(start + CHUNK, NN);
    int c = threadIdx.x;
    int g = batch[start];
    float acc = 0.f, count = 0.f;
    for (int n = start; n < end; n++) {
        int bg = batch[n];
        if (bg != g) {
            atomicAdd(&sums[g * HIDD + c], acc);
            if (c == 0) atomicAdd(&cnt[g], count);
            acc = 0.f; count = 0.f; g = bg;
        }
        acc += h[(size_t)n * HIDD + c];
        count += 1.f;
    }
    atomicAdd(&sums[g * HIDD + c], acc);
    if (c == 0) atomicAdd(&cnt[g], count);
}

__global__ void classifier_kernel(const float* __restrict__ sums, const float* __restrict__ cnt,
                                  const float* __restrict__ c1W, const float* __restrict__ c1b,
                                  const float* __restrict__ c2W, const float* __restrict__ c2b,
                                  float* __restrict__ out)
{
    __shared__ float p[HIDD];
    __shared__ float hid[64];
    __shared__ float lg[3];
    int g = blockIdx.x, t = threadIdx.x;
    float c = fmaxf(cnt[g], 1.f);
    float pv = sums[g * HIDD + t] / c;
    p[t] = pv;
    out[NGG * NCC + g * HIDD + t] = pv;
    __syncthreads();
    if (t < 64) {
        float s = c1b[t];
        #pragma unroll 4
        for (int k = 0; k < HIDD; k++) s += p[k] * c1W[k * 64 + t];
        hid[t] = fmaxf(s, 0.f);
    }
    __syncthreads();
    if (t < 3) {
        float s = c2b[t];
        #pragma unroll 4
        for (int k = 0; k < 64; k++) s += hid[k] * c2W[k * 3 + t];
        lg[t] = s;
        out[g * NCC + t] = s;
    }
    __syncthreads();
    if (t < 3) {
        float mx = fmaxf(fmaxf(lg[0], lg[1]), lg[2]);
        float e0 = expf(lg[0] - mx), e1 = expf(lg[1] - mx), e2 = expf(lg[2] - mx);
        float ev = (t == 0) ? e0 : ((t == 1) ? e1 : e2);
        out[NGG * NCC + NGG * HIDD + g * NCC + t] = ev / (e0 + e1 + e2);
    }
}

// --------------------------------- host --------------------------------
extern "C" void kernel_launch(void* const* d_in, const int* in_sizes, int n_in,
                              void* d_out, int out_size)
{
    const float* x      = (const float*)d_in[0];
    const int*   ei     = (const int*)d_in[1];
    const int*   batch  = (const int*)d_in[2];
    const float* memory = (const float*)d_in[3];
    const float* enc_W  = (const float*)d_in[4];
    const float* enc_b  = (const float*)d_in[5];
    const float* gat_W  = (const float*)d_in[6];
    const float* att_s  = (const float*)d_in[7];
    const float* att_d  = (const float*)d_in[8];
    const float* gat_b  = (const float*)d_in[9];
    const float* W_ih   = (const float*)d_in[10];
    const float* W_hh   = (const float*)d_in[11];
    const float* b_ih   = (const float*)d_in[12];
    const float* b_hh   = (const float*)d_in[13];
    const float* c1W    = (const float*)d_in[14];
    const float* c1b    = (const float*)d_in[15];
    const float* c2W    = (const float*)d_in[16];
    const float* c2b    = (const float*)d_in[17];
    float* out = (float*)d_out;

    float *p_h, *p_z, *p_as, *p_ad, *p_q, *p_gi, *p_gh, *p_pool, *p_cnt;
    int *p_deg, *p_off, *p_cur, *p_esrc;
    __nv_bfloat16 *p_bhi, *p_blo;
    cudaGetSymbolAddress((void**)&p_h,    g_h);
    cudaGetSymbolAddress((void**)&p_z,    g_z);
    cudaGetSymbolAddress((void**)&p_as,   g_as);
    cudaGetSymbolAddress((void**)&p_ad,   g_ad);
    cudaGetSymbolAddress((void**)&p_q,    g_q);
    cudaGetSymbolAddress((void**)&p_gi,   g_gi);
    cudaGetSymbolAddress((void**)&p_gh,   g_gh);
    cudaGetSymbolAddress((void**)&p_pool, g_pool);
    cudaGetSymbolAddress((void**)&p_cnt,  g_cnt);
    cudaGetSymbolAddress((void**)&p_deg,  g_deg);
    cudaGetSymbolAddress((void**)&p_off,  g_off);
    cudaGetSymbolAddress((void**)&p_cur,  g_cur);
    cudaGetSymbolAddress((void**)&p_esrc, g_esrc);
    cudaGetSymbolAddress((void**)&p_bhi,  g_bhi);
    cudaGetSymbolAddress((void**)&p_blo,  g_blo);

    const int MB = (NN + 127) / 128;   // 391

    // CSR build (reused across layers)
    cudaMemsetAsync(p_deg, 0, sizeof(int) * NN);
    cudaMemsetAsync(p_cur, 0, sizeof(int) * NN);
    csr_count<<<(ETOT + 255) / 256, 256>>>(ei, p_deg);
    csr_scan<<<1, 1024>>>(p_deg, p_off);
    csr_scatter<<<(ETOT + 255) / 256, 256>>>(ei, p_off, p_cur, p_esrc);

    // encoder: h = relu(x @ enc_W + enc_b)
    conv_trans128<<<(128 * 128 + 255) / 256, 256>>>(enc_W, p_bhi, p_blo);
    gemm_mma<<<dim3(1, MB), 256>>>(x, p_bhi, p_blo, enc_b, p_h, NN, 128, 128, 1.f, 1);

    for (int l = 0; l < NLL; l++) {
        const float* Wl = gat_W + (size_t)l * HIDD * NHH * HIDD;
        build_q<<<(2048 * 32 + 255) / 256, 256>>>(
            Wl, att_s + l * NHH * HIDD, att_d + l * NHH * HIDD, p_q);
        alpha2<<<(NN * 32 + 255) / 256, 256>>>(p_h, p_q, p_as, p_ad);
        conv_wl<<<(128 * 1024 + 255) / 256, 256>>>(Wl, p_bhi, p_blo);
        edge_agg<<<NN, 128>>>(p_off, p_esrc, p_as, p_ad, p_h, p_z);
        gemm_mma<<<dim3(1, MB), 256>>>(p_z, p_bhi, p_blo, gat_b + l * HIDD, p_h,
                                       NN, 1024, 128, 0.125f, (l < NLL - 1) ? 1 : 0);
    }

    // GRU gates
    conv_pass<<<(384 * 128 + 255) / 256, 256>>>(W_ih, p_bhi, p_blo, 384 * 128);
    gemm_mma<<<dim3(3, MB), 256>>>(p_h, p_bhi, p_blo, b_ih, p_gi, NN, 128, 384, 1.f, 0);
    conv_pass<<<(384 * 128 + 255) / 256, 256>>>(W_hh, p_bhi, p_blo, 384 * 128);
    gemm_mma<<<dim3(3, MB), 256>>>(memory, p_bhi, p_blo, b_hh, p_gh, NN, 128, 384, 1.f, 0);
    gru_kernel<<<((size_t)NN * HIDD + 255) / 256, 256>>>(p_gi, p_gh, memory, p_h);

    // pooling + classifier
    cudaMemsetAsync(p_pool, 0, sizeof(float) * NGG * HIDD);
    cudaMemsetAsync(p_cnt,  0, sizeof(float) * NGG);
    pool_kernel<<<(NN + 499) / 500, 128>>>(p_h, batch, p_pool, p_cnt);
    classifier_kernel<<<NGG, HIDD>>>(p_pool, p_cnt, c1W, c1b, c2W, c2b, out);
}